// round 1
// baseline (speedup 1.0000x reference)
#include <cuda_runtime.h>

#define FULLMASK 0xffffffffu

__device__ __forceinline__ float redsum16(float v) {
    v += __shfl_xor_sync(FULLMASK, v, 8);
    v += __shfl_xor_sync(FULLMASK, v, 4);
    v += __shfl_xor_sync(FULLMASK, v, 2);
    v += __shfl_xor_sync(FULLMASK, v, 1);
    return v;
}

__device__ __forceinline__ float redmax16(float v) {
    v = fmaxf(v, __shfl_xor_sync(FULLMASK, v, 8));
    v = fmaxf(v, __shfl_xor_sync(FULLMASK, v, 4));
    v = fmaxf(v, __shfl_xor_sync(FULLMASK, v, 2));
    v = fmaxf(v, __shfl_xor_sync(FULLMASK, v, 1));
    return v;
}

// One warp per patch. Patch = 32 channels x 64 contiguous floats = 512 float4.
// Lane groups of 4 read 64B contiguous chunks: 8 lines per LDG.128 (good L1tex wf count).
__global__ void __launch_bounds__(256) router_kernel(
    const float* __restrict__ patch,
    const float* __restrict__ keys,
    const float* __restrict__ p_temp,
    const float* __restrict__ p_beta,
    const float* __restrict__ p_thr,
    float* __restrict__ out,
    int n_patches)
{
    __shared__ float s_keys[16 * 33];     // padded stride 33 -> conflict-free spread reads
    __shared__ float s_raw[8][32];        // per-warp channel sums

    const int tid  = threadIdx.x;
    const int wid  = tid >> 5;
    const int lane = tid & 31;

    // Stage expert keys (16x32) into padded smem
    for (int i = tid; i < 16 * 32; i += blockDim.x) {
        int e = i >> 5, c = i & 31;
        s_keys[e * 33 + c] = keys[i];
    }
    __syncthreads();

    const int n = blockIdx.x * 8 + wid;
    if (n >= n_patches) return;          // whole warp exits together; no block syncs below

    const float logit_temp = __ldg(p_temp);
    const float mask_beta  = __ldg(p_beta);
    const float thr_base   = __ldg(p_thr);

    const float4* p4 = reinterpret_cast<const float4*>(patch) + (size_t)n * 512;

    // ---- Load: 16 x LDG.128, all issued up front for MLP ----
    // pass p (0..3): channel c = p*8 + (lane>>2), within-channel float4 j = (lane&3) + 4q
    float4 v[16];
#pragma unroll
    for (int t = 0; t < 16; t++) {
        const int p = t >> 2, q = t & 3;
        const int idx = p * 128 + (lane >> 2) * 16 + (lane & 3) + 4 * q;
        v[t] = p4[idx];
    }

    // ---- Per-pass channel reduction: 2 shfl per pass ----
#pragma unroll
    for (int p = 0; p < 4; p++) {
        float a = 0.0f;
#pragma unroll
        for (int q = 0; q < 4; q++) {
            const float4 x = v[p * 4 + q];
            a += (x.x + x.y) + (x.z + x.w);
        }
        a += __shfl_xor_sync(FULLMASK, a, 1);
        a += __shfl_xor_sync(FULLMASK, a, 2);
        if ((lane & 3) == 0)
            s_raw[wid][p * 8 + (lane >> 2)] = a;   // raw channel sum (mean * 64)
    }
    __syncwarp();

    // ---- L2 norm of raw channel sums ----
    // emb = raw/64; normalized emb = raw / max(||raw||, 64*1e-12)
    float rc = s_raw[wid][lane];
    float sq = rc * rc;
    sq += __shfl_xor_sync(FULLMASK, sq, 16);
    sq += __shfl_xor_sync(FULLMASK, sq, 8);
    sq += __shfl_xor_sync(FULLMASK, sq, 4);
    sq += __shfl_xor_sync(FULLMASK, sq, 2);
    sq += __shfl_xor_sync(FULLMASK, sq, 1);
    const float denom = fmaxf(sqrtf(sq), 64.0f * 1e-12f);

    // ---- Logits: lane e = lane&15 computes expert e (both halves mirror) ----
    const int e = lane & 15;
    float dot = 0.0f;
#pragma unroll
    for (int c = 0; c < 32; c++)
        dot = fmaf(s_raw[wid][c], s_keys[e * 33 + c], dot);   // s_raw read is broadcast

    const float sl = (dot / denom) / logit_temp + 1e-8f;

    // ---- Softmax over 16 ----
    const float m  = redmax16(sl);
    const float ex = __expf(sl - m);
    const float S  = redsum16(ex);
    const float w  = ex / S;

    // ---- Rank of each weight (descending, stable) ----
    int rank = 0;
#pragma unroll
    for (int j = 0; j < 16; j++) {
        const float wj = __shfl_sync(FULLMASK, w, j, 16);
        rank += (wj > w) || (wj == w && j < e);
    }

    // ---- Order statistics & moments ----
    const float s0    = redsum16(rank == 0 ? w : 0.0f);                    // max weight
    const float rest  = redsum16((rank >= 1 && rank <= 4) ? w : 0.0f) * 0.25f;
    const float kth   = redsum16(rank == 3 ? w : 0.0f);                    // 4th largest
    const float meanw = redsum16(w) * (1.0f / 16.0f);
    const float d     = w - meanw;
    const float varw  = redsum16(d * d) * (1.0f / 15.0f);                  // ddof=1
    const float stdw  = sqrtf(varw);
    const float ent   = -redsum16(w * __logf(w + 1e-18f));

    // ---- Adaptive threshold ----
    const float maxc = 1.0f - s0;
    const float entc = 1.0f - ent * (1.0f / 2.7725887222397811f);          // 1/log(16)
    float gap = (s0 - rest) / (s0 + 1e-8f);
    gap = fminf(fmaxf(gap, 0.0f), 1.0f);
    const float af = 0.4f * maxc + 0.3f * entc + 0.3f * gap;
    float adaptive = thr_base * (0.5f + af);
    const float min_thr = fmaxf(0.05f, meanw - 0.5f * stdw);
    const float max_thr = fminf(0.7f, s0 - 0.1f * stdw);
    adaptive = fminf(fmaxf(adaptive, min_thr), max_thr);
    adaptive = fminf(adaptive, kth * 0.9f);

    // ---- Soft mask + renormalize ----
    const float x    = (mask_beta + 1e-8f) * (w - adaptive);
    const float sm   = 1.0f / (1.0f + __expf(-x));
    const float wf   = w * sm;
    const float swf  = redsum16(wf);
    const float o    = wf / fmaxf(swf, 1e-8f);

    if (lane < 16)
        out[(size_t)n * 16 + e] = o;
}

extern "C" void kernel_launch(void* const* d_in, const int* in_sizes, int n_in,
                              void* d_out, int out_size) {
    const float* patch = (const float*)d_in[0];
    const float* keys  = (const float*)d_in[1];
    const float* temp  = (const float*)d_in[2];
    const float* beta  = (const float*)d_in[3];
    const float* thr   = (const float*)d_in[4];
    float* out = (float*)d_out;

    const int n_patches = in_sizes[0] / (32 * 8 * 8);
    const int blocks = (n_patches + 7) / 8;   // 8 warps (patches) per 256-thread block
    router_kernel<<<blocks, 256>>>(patch, keys, temp, beta, thr, out, n_patches);
}